// round 3
// baseline (speedup 1.0000x reference)
#include <cuda_runtime.h>
#include <math.h>

#define NN 50000
#define EE 800000
#define FF 256

// ---------------- device scratch (no runtime allocation allowed) ------------
__device__ int   g_is64;
__device__ int   g_cnt[NN];
__device__ int   g_cursor[NN];
__device__ int   g_rowstart[NN + 1];
__device__ float g_dis[NN];
__device__ int   g_esrc[EE];
__device__ float g_enorm[EE];
__device__ float g_T [(size_t)NN * FF];
__device__ float g_HA[(size_t)NN * FF];
__device__ float g_HB[(size_t)NN * FF];
__device__ float g_t2[NN * 2];

// packed fp32x2 FMA (Blackwell FFMA2; PTX-only, ptxas never auto-fuses)
#define FMA2(c, a, b) \
    asm("fma.rn.f32x2 %0, %1, %2, %0;" : "+l"(c) : "l"(a), "l"(b))

// ---------------- small helpers ---------------------------------------------
__device__ __forceinline__ int load_edge(const void* ei, long long idx) {
    if (g_is64) return (int)((const long long*)ei)[idx];
    return ((const int*)ei)[idx];
}

// Detect int64 vs int32 edge_index (values < 2^31 -> odd 32-bit words zero).
__global__ void k_detect(const int* p) {
    if (threadIdx.x == 0) {
        int any = 0;
        #pragma unroll
        for (int i = 1; i < 64; i += 2) any |= p[i];
        g_is64 = (any == 0) ? 1 : 0;
    }
}

__global__ void k_init_counts() {
    int i = blockIdx.x * blockDim.x + threadIdx.x;
    if (i < NN) { g_cnt[i] = 0; g_cursor[i] = 0; }
}

__global__ void k_count(const void* ei) {
    int e = blockIdx.x * blockDim.x + threadIdx.x;
    if (e >= EE) return;
    int dst = load_edge(ei, (long long)EE + e);
    atomicAdd(&g_cnt[dst], 1);
}

__global__ void k_dis() {
    int i = blockIdx.x * blockDim.x + threadIdx.x;
    if (i < NN) g_dis[i] = rsqrtf((float)(g_cnt[i] + 1));  // +1 self-loop
}

// Exclusive scan of g_cnt -> g_rowstart. One block: thread-sequential chunks +
// warp-shuffle block scan (2 barriers total instead of ~980).
#define SCAN_PER 49  // 1024 * 49 = 50176 >= NN
__global__ void k_scan() {
    __shared__ int warptot[32];
    int tid  = threadIdx.x;
    int lane = tid & 31;
    int wid  = tid >> 5;
    int base = tid * SCAN_PER;

    // pass 1: per-thread total
    int sum = 0;
    #pragma unroll 7
    for (int i = 0; i < SCAN_PER; i++) {
        int idx = base + i;
        sum += (idx < NN) ? g_cnt[idx] : 0;
    }

    // warp inclusive scan
    int x = sum;
    #pragma unroll
    for (int off = 1; off < 32; off <<= 1) {
        int n = __shfl_up_sync(0xffffffffu, x, off);
        if (lane >= off) x += n;
    }
    if (lane == 31) warptot[wid] = x;
    __syncthreads();
    if (wid == 0) {
        int w = warptot[lane];
        #pragma unroll
        for (int off = 1; off < 32; off <<= 1) {
            int n = __shfl_up_sync(0xffffffffu, w, off);
            if (lane >= off) w += n;
        }
        warptot[lane] = w;  // inclusive warp sums
    }
    __syncthreads();

    int offset = x - sum;                       // exclusive within warp
    if (wid > 0) offset += warptot[wid - 1];    // + preceding warps

    // pass 2: write exclusive prefixes (covers index NN as the total)
    int running = offset;
    #pragma unroll 7
    for (int i = 0; i < SCAN_PER; i++) {
        int idx = base + i;
        if (idx <= NN) g_rowstart[idx] = running;
        running += (idx < NN) ? g_cnt[idx] : 0;
    }
}

// Bucket edges by destination (CSR) + per-edge norm.
__global__ void k_build(const void* ei) {
    int e = blockIdx.x * blockDim.x + threadIdx.x;
    if (e >= EE) return;
    int src = load_edge(ei, e);
    int dst = load_edge(ei, (long long)EE + e);
    float w = g_dis[src] * g_dis[dst];
    int pos = g_rowstart[dst] + atomicAdd(&g_cursor[dst], 1);
    g_esrc[pos]  = src;
    g_enorm[pos] = w;
}

// ---------------- dense GEMM: C[N,256] = (relu?)A[N,256] @ W[256,256] --------
// f32x2 packed-FMA version: accumulators pair adjacent output COLUMNS.
// B pairs come free (consecutive floats in Bs); A is stored DUPLICATED in
// shared so one 128-bit LDS yields two ready {a,a} pairs -> zero pack instrs.
#define BM 128
#define BN 128
#define BK 16
#define AS_STRIDE (2 * BM + 4)   // 260 floats: keeps 16B alignment, de-phases banks

template <bool RELU>
__global__ __launch_bounds__(256, 2) void k_gemm(const float* __restrict__ A,
                                                 const float* __restrict__ Wm,
                                                 float* __restrict__ C,
                                                 int nrows) {
    __shared__ float As2[BK * AS_STRIDE];   // duplicated A tile
    __shared__ float Bs[BK][BN];
    int tid = threadIdx.x;
    int rowBase = blockIdx.x * BM;
    int colBase = blockIdx.y * BN;
    int tx = tid & 15;
    int ty = tid >> 4;

    unsigned long long acc[8][4];  // each = packed {C[i][2j], C[i][2j+1]}
    #pragma unroll
    for (int i = 0; i < 8; i++)
        #pragma unroll
        for (int j = 0; j < 4; j++) acc[i][j] = 0ull;

    for (int k0 = 0; k0 < 256; k0 += BK) {
        // A tile: 128x16, duplicated store As2[k][2r]=As2[k][2r+1]=a
        #pragma unroll
        for (int l = 0; l < 2; l++) {
            int id = tid + l * 256;
            int r  = id >> 2;
            int q  = id & 3;
            int row = rowBase + r;
            float4 v = make_float4(0.f, 0.f, 0.f, 0.f);
            if (row < nrows)
                v = *(const float4*)(A + (size_t)row * 256 + k0 + q * 4);
            if (RELU) {
                v.x = fmaxf(v.x, 0.f); v.y = fmaxf(v.y, 0.f);
                v.z = fmaxf(v.z, 0.f); v.w = fmaxf(v.w, 0.f);
            }
            *(float2*)&As2[(q * 4 + 0) * AS_STRIDE + 2 * r] = make_float2(v.x, v.x);
            *(float2*)&As2[(q * 4 + 1) * AS_STRIDE + 2 * r] = make_float2(v.y, v.y);
            *(float2*)&As2[(q * 4 + 2) * AS_STRIDE + 2 * r] = make_float2(v.z, v.z);
            *(float2*)&As2[(q * 4 + 3) * AS_STRIDE + 2 * r] = make_float2(v.w, v.w);
        }
        // B tile: 16x128, direct
        #pragma unroll
        for (int l = 0; l < 2; l++) {
            int id = tid + l * 256;
            int kk = id >> 5;
            int c4 = id & 31;
            float4 v = *(const float4*)(Wm + (size_t)(k0 + kk) * 256 + colBase + c4 * 4);
            *(float4*)&Bs[kk][c4 * 4] = v;
        }
        __syncthreads();

        #pragma unroll
        for (int kk = 0; kk < BK; kk++) {
            // 8 duplicated a-pairs (4 x 128-bit LDS, broadcast within warp)
            ulonglong2 a01 = *(const ulonglong2*)&As2[kk * AS_STRIDE + ty * 16 + 0];
            ulonglong2 a23 = *(const ulonglong2*)&As2[kk * AS_STRIDE + ty * 16 + 4];
            ulonglong2 a45 = *(const ulonglong2*)&As2[kk * AS_STRIDE + ty * 16 + 8];
            ulonglong2 a67 = *(const ulonglong2*)&As2[kk * AS_STRIDE + ty * 16 + 12];
            unsigned long long ad[8] = {a01.x, a01.y, a23.x, a23.y,
                                        a45.x, a45.y, a67.x, a67.y};
            // 4 natural b-pairs (2 x 128-bit LDS)
            ulonglong2 b01 = *(const ulonglong2*)&Bs[kk][tx * 8];
            ulonglong2 b23 = *(const ulonglong2*)&Bs[kk][tx * 8 + 4];
            unsigned long long bd[4] = {b01.x, b01.y, b23.x, b23.y};

            #pragma unroll
            for (int i = 0; i < 8; i++) {
                FMA2(acc[i][0], ad[i], bd[0]);
                FMA2(acc[i][1], ad[i], bd[1]);
                FMA2(acc[i][2], ad[i], bd[2]);
                FMA2(acc[i][3], ad[i], bd[3]);
            }
        }
        __syncthreads();
    }

    #pragma unroll
    for (int i = 0; i < 8; i++) {
        int row = rowBase + ty * 8 + i;
        if (row < nrows) {
            float* cp = C + (size_t)row * 256 + colBase + tx * 8;
            *(ulonglong2*)cp       = make_ulonglong2(acc[i][0], acc[i][1]);
            *(ulonglong2*)(cp + 4) = make_ulonglong2(acc[i][2], acc[i][3]);
        }
    }
}

// ---------------- aggregation, F=256: warp per node, CSR, no atomics --------
__global__ void k_agg(const float4* __restrict__ T4,
                      const float*  __restrict__ bias,
                      float4* __restrict__ O4) {
    int warp = (blockIdx.x * blockDim.x + threadIdx.x) >> 5;
    int lane = threadIdx.x & 31;
    if (warp >= NN) return;
    int node = warp;

    float ws = g_dis[node];
    ws *= ws;  // self-loop weight dis^2 = 1/deg

    float4 a0 = T4[(size_t)node * 64 + lane];
    float4 a1 = T4[(size_t)node * 64 + lane + 32];
    float4 acc0 = make_float4(a0.x * ws, a0.y * ws, a0.z * ws, a0.w * ws);
    float4 acc1 = make_float4(a1.x * ws, a1.y * ws, a1.z * ws, a1.w * ws);

    int p0 = g_rowstart[node];
    int p1 = g_rowstart[node + 1];
    for (int p = p0; p < p1; p++) {
        int   s = g_esrc[p];
        float w = g_enorm[p];
        float4 v0 = T4[(size_t)s * 64 + lane];
        float4 v1 = T4[(size_t)s * 64 + lane + 32];
        acc0.x = fmaf(v0.x, w, acc0.x); acc0.y = fmaf(v0.y, w, acc0.y);
        acc0.z = fmaf(v0.z, w, acc0.z); acc0.w = fmaf(v0.w, w, acc0.w);
        acc1.x = fmaf(v1.x, w, acc1.x); acc1.y = fmaf(v1.y, w, acc1.y);
        acc1.z = fmaf(v1.z, w, acc1.z); acc1.w = fmaf(v1.w, w, acc1.w);
    }

    float4 b0 = ((const float4*)bias)[lane];
    float4 b1 = ((const float4*)bias)[lane + 32];
    acc0.x += b0.x; acc0.y += b0.y; acc0.z += b0.z; acc0.w += b0.w;
    acc1.x += b1.x; acc1.y += b1.y; acc1.z += b1.z; acc1.w += b1.w;
    O4[(size_t)node * 64 + lane]      = acc0;
    O4[(size_t)node * 64 + lane + 32] = acc1;
}

// ---------------- last layer: t2[N,2] = relu(A) @ W3[256,2] ------------------
__global__ void k_gemm2(const float* __restrict__ A,
                        const float* __restrict__ W3,
                        float* __restrict__ t2) {
    int warp = (blockIdx.x * blockDim.x + threadIdx.x) >> 5;
    int lane = threadIdx.x & 31;
    if (warp >= NN) return;
    const float* row = A + (size_t)warp * 256;
    float s0 = 0.f, s1 = 0.f;
    #pragma unroll
    for (int k = lane; k < 256; k += 32) {
        float h = fmaxf(row[k], 0.f);
        float2 w = ((const float2*)W3)[k];
        s0 = fmaf(h, w.x, s0);
        s1 = fmaf(h, w.y, s1);
    }
    #pragma unroll
    for (int off = 16; off; off >>= 1) {
        s0 += __shfl_xor_sync(0xffffffffu, s0, off);
        s1 += __shfl_xor_sync(0xffffffffu, s1, off);
    }
    if (lane == 0) { t2[warp * 2] = s0; t2[warp * 2 + 1] = s1; }
}

// ---------------- final aggregation (F=2) into d_out -------------------------
__global__ void k_agg2(const float* __restrict__ t2,
                       const float* __restrict__ b3,
                       float* __restrict__ out) {
    int warp = (blockIdx.x * blockDim.x + threadIdx.x) >> 5;
    int lane = threadIdx.x & 31;
    if (warp >= NN) return;
    int node = warp;
    int p0 = g_rowstart[node];
    int p1 = g_rowstart[node + 1];
    float s0 = 0.f, s1 = 0.f;
    for (int p = p0 + lane; p < p1; p += 32) {
        int   s = g_esrc[p];
        float w = g_enorm[p];
        s0 = fmaf(t2[s * 2],     w, s0);
        s1 = fmaf(t2[s * 2 + 1], w, s1);
    }
    #pragma unroll
    for (int off = 16; off; off >>= 1) {
        s0 += __shfl_xor_sync(0xffffffffu, s0, off);
        s1 += __shfl_xor_sync(0xffffffffu, s1, off);
    }
    if (lane == 0) {
        float ws = g_dis[node];
        ws *= ws;
        out[node * 2]     = s0 + t2[node * 2]     * ws + b3[0];
        out[node * 2 + 1] = s1 + t2[node * 2 + 1] * ws + b3[1];
    }
}

// ---------------- launch ------------------------------------------------------
extern "C" void kernel_launch(void* const* d_in, const int* in_sizes, int n_in,
                              void* d_out, int out_size) {
    const float* x  = (const float*)d_in[0];
    const void*  ei = d_in[1];
    const float* W0 = (const float*)d_in[2];
    const float* b0 = (const float*)d_in[3];
    const float* W1 = (const float*)d_in[4];
    const float* b1 = (const float*)d_in[5];
    const float* W2 = (const float*)d_in[6];
    const float* b2 = (const float*)d_in[7];
    const float* W3 = (const float*)d_in[8];
    const float* b3 = (const float*)d_in[9];
    float* out = (float*)d_out;

    float *T, *HA, *HB, *t2;
    cudaGetSymbolAddress((void**)&T,  g_T);
    cudaGetSymbolAddress((void**)&HA, g_HA);
    cudaGetSymbolAddress((void**)&HB, g_HB);
    cudaGetSymbolAddress((void**)&t2, g_t2);

    const int nodeBlocks = (NN + 255) / 256;       // 196
    const int edgeBlocks = (EE + 255) / 256;       // 3125
    const int warpBlocks = (NN + 7) / 8;           // 6250 (8 warps / 256-thr block)
    dim3 gemmGrid((NN + BM - 1) / BM, 256 / BN);   // (391, 2)

    // ---- graph preprocessing (replayed every call; cheap) ----
    k_detect<<<1, 32>>>((const int*)ei);
    k_init_counts<<<nodeBlocks, 256>>>();
    k_count<<<edgeBlocks, 256>>>(ei);
    k_dis<<<nodeBlocks, 256>>>();
    k_scan<<<1, 1024>>>();
    k_build<<<edgeBlocks, 256>>>(ei);

    // ---- layer 1: x @ W0 -> T ; aggregate+bias -> HA (relu deferred) ----
    k_gemm<false><<<gemmGrid, 256>>>(x, W0, T, NN);
    k_agg<<<warpBlocks, 256>>>((const float4*)T, b0, (float4*)HA);

    // ---- layer 2 ----
    k_gemm<true><<<gemmGrid, 256>>>(HA, W1, T, NN);
    k_agg<<<warpBlocks, 256>>>((const float4*)T, b1, (float4*)HB);

    // ---- layer 3 ----
    k_gemm<true><<<gemmGrid, 256>>>(HB, W2, T, NN);
    k_agg<<<warpBlocks, 256>>>((const float4*)T, b2, (float4*)HA);

    // ---- layer 4: relu(HA) @ W3 -> t2 ; aggregate F=2 -> out ----
    k_gemm2<<<warpBlocks, 256>>>(HA, W3, t2);
    k_agg2<<<warpBlocks, 256>>>(t2, b3, out);
}

// round 11
// speedup vs baseline: 1.4940x; 1.4940x over previous
#include <cuda_runtime.h>
#include <cuda_bf16.h>
#include <math.h>
#include <stdint.h>

#define NN 50000
#define EE 800000
#define FF 256
#define NTILES 391  // ceil(50000/128)

// ---------------- device scratch (no runtime allocation allowed) ------------
__device__ int   g_is64;
__device__ int   g_cnt[NN];
__device__ int   g_cursor[NN];
__device__ int   g_rowstart[NN + 1];
__device__ float g_dis[NN];
__device__ int   g_esrc[EE];
__device__ float g_enorm[EE];
__device__ float g_T [(size_t)NN * FF];
__device__ float g_HA[(size_t)NN * FF];
__device__ float g_HB[(size_t)NN * FF];
__device__ float g_t2[NN * 2];
__device__ __nv_bfloat16 g_Whi[3][FF * FF];  // W^T split-high, [n][k]
__device__ __nv_bfloat16 g_Wlo[3][FF * FF];  // W^T split-low,  [n][k]

// ---------------- small helpers ---------------------------------------------
__device__ __forceinline__ int load_edge(const void* ei, long long idx) {
    if (g_is64) return (int)((const long long*)ei)[idx];
    return ((const int*)ei)[idx];
}

__global__ void k_detect(const int* p) {
    if (threadIdx.x == 0) {
        int any = 0;
        #pragma unroll
        for (int i = 1; i < 64; i += 2) any |= p[i];
        g_is64 = (any == 0) ? 1 : 0;
    }
}

__global__ void k_init_counts() {
    int i = blockIdx.x * blockDim.x + threadIdx.x;
    if (i < NN) { g_cnt[i] = 0; g_cursor[i] = 0; }
}

__global__ void k_count(const void* ei) {
    int e = blockIdx.x * blockDim.x + threadIdx.x;
    if (e >= EE) return;
    int dst = load_edge(ei, (long long)EE + e);
    atomicAdd(&g_cnt[dst], 1);
}

__global__ void k_dis() {
    int i = blockIdx.x * blockDim.x + threadIdx.x;
    if (i < NN) g_dis[i] = rsqrtf((float)(g_cnt[i] + 1));
}

#define SCAN_PER 49
__global__ void k_scan() {
    __shared__ int warptot[32];
    int tid  = threadIdx.x;
    int lane = tid & 31;
    int wid  = tid >> 5;
    int base = tid * SCAN_PER;
    int sum = 0;
    #pragma unroll 7
    for (int i = 0; i < SCAN_PER; i++) {
        int idx = base + i;
        sum += (idx < NN) ? g_cnt[idx] : 0;
    }
    int x = sum;
    #pragma unroll
    for (int off = 1; off < 32; off <<= 1) {
        int n = __shfl_up_sync(0xffffffffu, x, off);
        if (lane >= off) x += n;
    }
    if (lane == 31) warptot[wid] = x;
    __syncthreads();
    if (wid == 0) {
        int w = warptot[lane];
        #pragma unroll
        for (int off = 1; off < 32; off <<= 1) {
            int n = __shfl_up_sync(0xffffffffu, w, off);
            if (lane >= off) w += n;
        }
        warptot[lane] = w;
    }
    __syncthreads();
    int offset = x - sum;
    if (wid > 0) offset += warptot[wid - 1];
    int running = offset;
    #pragma unroll 7
    for (int i = 0; i < SCAN_PER; i++) {
        int idx = base + i;
        if (idx <= NN) g_rowstart[idx] = running;
        running += (idx < NN) ? g_cnt[idx] : 0;
    }
}

__global__ void k_build(const void* ei) {
    int e = blockIdx.x * blockDim.x + threadIdx.x;
    if (e >= EE) return;
    int src = load_edge(ei, e);
    int dst = load_edge(ei, (long long)EE + e);
    float w = g_dis[src] * g_dis[dst];
    int pos = g_rowstart[dst] + atomicAdd(&g_cursor[dst], 1);
    g_esrc[pos]  = src;
    g_enorm[pos] = w;
}

// --------- weight split/transpose: Whi[n][k]+Wlo[n][k] = W[k][n] ------------
__global__ void k_wsplit(const float* __restrict__ W,
                         __nv_bfloat16* __restrict__ bhi,
                         __nv_bfloat16* __restrict__ blo) {
    int i = blockIdx.x * 256 + threadIdx.x;  // i = k*256 + n
    int k = i >> 8, n = i & 255;
    float w = W[i];
    __nv_bfloat16 h = __float2bfloat16_rn(w);
    __nv_bfloat16 l = __float2bfloat16_rn(w - __bfloat162float(h));
    bhi[n * 256 + k] = h;
    blo[n * 256 + k] = l;
}

// ---------------- mma.sync GEMM (sm_80 path; works on plain sm_103) ---------
// C[N,256] = (relu?)A[N,256] @ W[256,256], split-bf16 x3 passes, fp32 accum.
// Block 128(M)x128(N), 8 warps (2M x 4N), warp tile 64x32, K chunk 64.
#define AST 72    // A smem row stride (bf16): 36 words, mod32=4 -> conflict-free
#define WST 264   // W smem row stride (bf16): 132 words, mod32=4 -> conflict-free
#define SM_W  (128 * WST * 2)          // 67584 B per half (hi or lo)
#define SM_A  (128 * AST * 2)          // 18432 B per half
#define SM_TOT (2 * SM_W + 2 * SM_A)   // 172032 B

__device__ __forceinline__ void mma_bf16(float c[4], const uint32_t a[4],
                                         const uint32_t b[2]) {
    asm volatile(
        "mma.sync.aligned.m16n8k16.row.col.f32.bf16.bf16.f32 "
        "{%0,%1,%2,%3}, {%4,%5,%6,%7}, {%8,%9}, {%0,%1,%2,%3};"
        : "+f"(c[0]), "+f"(c[1]), "+f"(c[2]), "+f"(c[3])
        : "r"(a[0]), "r"(a[1]), "r"(a[2]), "r"(a[3]), "r"(b[0]), "r"(b[1]));
}

template <bool RELU>
__global__ __launch_bounds__(256, 1)
void k_gemm_mma(const float* __restrict__ A,
                const __nv_bfloat16* __restrict__ WThi,
                const __nv_bfloat16* __restrict__ WTlo,
                float* __restrict__ C) {
    extern __shared__ __align__(16) char smem[];
    __nv_bfloat16* sWhi = (__nv_bfloat16*)smem;
    __nv_bfloat16* sWlo = sWhi + 128 * WST;
    __nv_bfloat16* sAhi = sWlo + 128 * WST;
    __nv_bfloat16* sAlo = sAhi + 128 * AST;

    const int tid  = threadIdx.x;
    const int wid  = tid >> 5;
    const int lane = tid & 31;
    const int g    = lane >> 2;   // group id (row/col within fragment)
    const int cc   = lane & 3;    // thread-in-group
    const int warpM = wid & 1;
    const int warpN = wid >> 1;
    const int rowBase = blockIdx.x * 128;
    const int nGlob   = blockIdx.y * 128;

    // ---- stage W^T half (128 n-rows x 256 k), hi+lo, once per block ----
    {
        const __nv_bfloat16* srcH = WThi + (size_t)nGlob * 256;
        const __nv_bfloat16* srcL = WTlo + (size_t)nGlob * 256;
        #pragma unroll
        for (int it = 0; it < 16; it++) {
            int idx = tid + it * 256;          // 128*32 16B-chunks
            int n  = idx >> 5;
            int kq = idx & 31;                 // 8-bf16 chunk
            *(uint4*)(sWhi + n * WST + kq * 8) =
                *(const uint4*)(srcH + n * 256 + kq * 8);
            *(uint4*)(sWlo + n * WST + kq * 8) =
                *(const uint4*)(srcL + n * 256 + kq * 8);
        }
    }

    float acc[4][4][4];
    #pragma unroll
    for (int i = 0; i < 4; i++)
        #pragma unroll
        for (int j = 0; j < 4; j++)
            #pragma unroll
            for (int q = 0; q < 4; q++) acc[i][j][q] = 0.f;

    const int rS = tid >> 1;    // staging row 0..127
    const int hS = tid & 1;     // staging k-half (32 fp32)
    const bool vS = (rowBase + rS) < NN;

    for (int kc = 0; kc < 4; kc++) {
        __syncthreads();  // W staged (it=0) / previous chunk consumed
        // ---- stage A chunk: 128 rows x 64 k, fp32 -> split bf16, relu ----
        {
            const float* src = A + (size_t)(rowBase + rS) * 256 + kc * 64 + hS * 32;
            __nv_bfloat16* dH = sAhi + rS * AST + hS * 32;
            __nv_bfloat16* dL = sAlo + rS * AST + hS * 32;
            #pragma unroll
            for (int q = 0; q < 4; q++) {   // 8 fp32 per iter
                float4 f0 = vS ? *(const float4*)(src + q * 8)
                               : make_float4(0.f, 0.f, 0.f, 0.f);
                float4 f1 = vS ? *(const float4*)(src + q * 8 + 4)
                               : make_float4(0.f, 0.f, 0.f, 0.f);
                if (RELU) {
                    f0.x = fmaxf(f0.x, 0.f); f0.y = fmaxf(f0.y, 0.f);
                    f0.z = fmaxf(f0.z, 0.f); f0.w = fmaxf(f0.w, 0.f);
                    f1.x = fmaxf(f1.x, 0.f); f1.y = fmaxf(f1.y, 0.f);
                    f1.z = fmaxf(f1.z, 0.f); f1.w = fmaxf(f1.w, 0.f);
                }
                __nv_bfloat162 h0 = __float22bfloat162_rn(make_float2(f0.x, f0.y));
                __nv_bfloat162 h1 = __float22bfloat162_rn(make_float2(f0.z, f0.w));
                __nv_bfloat162 h2 = __float22bfloat162_rn(make_float2(f1.x, f1.y));
                __nv_bfloat162 h3 = __float22bfloat162_rn(make_float2(f1.z, f1.w));
                __nv_bfloat162 l0 = __float22bfloat162_rn(make_float2(
                    f0.x - __bfloat162float(h0.x), f0.y - __bfloat162float(h0.y)));
                __nv_bfloat162 l1 = __float22bfloat162_rn(make_float2(
                    f0.z - __bfloat162float(h1.x), f0.w - __bfloat162float(h1.y)));
                __nv_bfloat162 l2 = __float22bfloat162_rn(make_float2(
                    f1.x - __bfloat162float(h2.x), f1.y - __bfloat162float(h2.y)));
                __nv_bfloat162 l3 = __float22bfloat162_rn(make_float2(
                    f1.z - __bfloat162float(h3.x), f1.w - __bfloat162float(h3.y)));
                ((__nv_bfloat162*)(dH + q * 8))[0] = h0;
                ((__nv_bfloat162*)(dH + q * 8))[1] = h1;
                ((__nv_bfloat162*)(dH + q * 8))[2] = h2;
                ((__nv_bfloat162*)(dH + q * 8))[3] = h3;
                ((__nv_bfloat162*)(dL + q * 8))[0] = l0;
                ((__nv_bfloat162*)(dL + q * 8))[1] = l1;
                ((__nv_bfloat162*)(dL + q * 8))[2] = l2;
                ((__nv_bfloat162*)(dL + q * 8))[3] = l3;
            }
        }
        __syncthreads();

        #pragma unroll
        for (int ks = 0; ks < 4; ks++) {
            const int ka = ks * 16 + 2 * cc;            // within A chunk
            const int kw = kc * 64 + ks * 16 + 2 * cc;  // within full W row
            uint32_t ah[4][4], al[4][4], bh[4][2], bl[4][2];
            #pragma unroll
            for (int i = 0; i < 4; i++) {
                const __nv_bfloat16* p =
                    sAhi + (warpM * 64 + i * 16 + g) * AST + ka;
                ah[i][0] = *(const uint32_t*)p;
                ah[i][1] = *(const uint32_t*)(p + 8 * AST);
                ah[i][2] = *(const uint32_t*)(p + 8);
                ah[i][3] = *(const uint32_t*)(p + 8 * AST + 8);
                const __nv_bfloat16* q =
                    sAlo + (warpM * 64 + i * 16 + g) * AST + ka;
                al[i][0] = *(const uint32_t*)q;
                al[i][1] = *(const uint32_t*)(q + 8 * AST);
                al[i][2] = *(const uint32_t*)(q + 8);
                al[i][3] = *(const uint32_t*)(q + 8 * AST + 8);
            }
            #pragma unroll
            for (int j = 0; j < 4; j++) {
                const __nv_bfloat16* p =
                    sWhi + (warpN * 32 + j * 8 + g) * WST + kw;
                bh[j][0] = *(const uint32_t*)p;
                bh[j][1] = *(const uint32_t*)(p + 8);
                const __nv_bfloat16* q =
                    sWlo + (warpN * 32 + j * 8 + g) * WST + kw;
                bl[j][0] = *(const uint32_t*)q;
                bl[j][1] = *(const uint32_t*)(q + 8);
            }
            #pragma unroll
            for (int i = 0; i < 4; i++)
                #pragma unroll
                for (int j = 0; j < 4; j++) {
                    mma_bf16(acc[i][j], ah[i], bh[j]);
                    mma_bf16(acc[i][j], al[i], bh[j]);
                    mma_bf16(acc[i][j], ah[i], bl[j]);
                }
        }
    }

    // ---- epilogue: fragment -> gmem (fp32) ----
    #pragma unroll
    for (int i = 0; i < 4; i++) {
        int row0 = rowBase + warpM * 64 + i * 16 + g;
        int row1 = row0 + 8;
        #pragma unroll
        for (int j = 0; j < 4; j++) {
            int col = nGlob + warpN * 32 + j * 8 + 2 * cc;
            if (row0 < NN)
                *(float2*)(C + (size_t)row0 * 256 + col) =
                    make_float2(acc[i][j][0], acc[i][j][1]);
            if (row1 < NN)
                *(float2*)(C + (size_t)row1 * 256 + col) =
                    make_float2(acc[i][j][2], acc[i][j][3]);
        }
    }
}

// ---------------- aggregation, F=256: warp per node, CSR, no atomics --------
__global__ void k_agg(const float4* __restrict__ T4,
                      const float*  __restrict__ bias,
                      float4* __restrict__ O4) {
    int warp = (blockIdx.x * blockDim.x + threadIdx.x) >> 5;
    int lane = threadIdx.x & 31;
    if (warp >= NN) return;
    int node = warp;
    float ws = g_dis[node];
    ws *= ws;
    float4 a0 = T4[(size_t)node * 64 + lane];
    float4 a1 = T4[(size_t)node * 64 + lane + 32];
    float4 acc0 = make_float4(a0.x * ws, a0.y * ws, a0.z * ws, a0.w * ws);
    float4 acc1 = make_float4(a1.x * ws, a1.y * ws, a1.z * ws, a1.w * ws);
    int p0 = g_rowstart[node];
    int p1 = g_rowstart[node + 1];
    for (int p = p0; p < p1; p++) {
        int   s = g_esrc[p];
        float w = g_enorm[p];
        float4 v0 = T4[(size_t)s * 64 + lane];
        float4 v1 = T4[(size_t)s * 64 + lane + 32];
        acc0.x = fmaf(v0.x, w, acc0.x); acc0.y = fmaf(v0.y, w, acc0.y);
        acc0.z = fmaf(v0.z, w, acc0.z); acc0.w = fmaf(v0.w, w, acc0.w);
        acc1.x = fmaf(v1.x, w, acc1.x); acc1.y = fmaf(v1.y, w, acc1.y);
        acc1.z = fmaf(v1.z, w, acc1.z); acc1.w = fmaf(v1.w, w, acc1.w);
    }
    float4 b0 = ((const float4*)bias)[lane];
    float4 b1 = ((const float4*)bias)[lane + 32];
    acc0.x += b0.x; acc0.y += b0.y; acc0.z += b0.z; acc0.w += b0.w;
    acc1.x += b1.x; acc1.y += b1.y; acc1.z += b1.z; acc1.w += b1.w;
    O4[(size_t)node * 64 + lane]      = acc0;
    O4[(size_t)node * 64 + lane + 32] = acc1;
}

// ---------------- last layer: t2[N,2] = relu(A) @ W3[256,2] ------------------
__global__ void k_gemm2(const float* __restrict__ A,
                        const float* __restrict__ W3,
                        float* __restrict__ t2) {
    int warp = (blockIdx.x * blockDim.x + threadIdx.x) >> 5;
    int lane = threadIdx.x & 31;
    if (warp >= NN) return;
    const float* row = A + (size_t)warp * 256;
    float s0 = 0.f, s1 = 0.f;
    #pragma unroll
    for (int k = lane; k < 256; k += 32) {
        float h = fmaxf(row[k], 0.f);
        float2 w = ((const float2*)W3)[k];
        s0 = fmaf(h, w.x, s0);
        s1 = fmaf(h, w.y, s1);
    }
    #pragma unroll
    for (int off = 16; off; off >>= 1) {
        s0 += __shfl_xor_sync(0xffffffffu, s0, off);
        s1 += __shfl_xor_sync(0xffffffffu, s1, off);
    }
    if (lane == 0) { t2[warp * 2] = s0; t2[warp * 2 + 1] = s1; }
}

// ---------------- final aggregation (F=2) into d_out -------------------------
__global__ void k_agg2(const float* __restrict__ t2,
                       const float* __restrict__ b3,
                       float* __restrict__ out) {
    int warp = (blockIdx.x * blockDim.x + threadIdx.x) >> 5;
    int lane = threadIdx.x & 31;
    if (warp >= NN) return;
    int node = warp;
    int p0 = g_rowstart[node];
    int p1 = g_rowstart[node + 1];
    float s0 = 0.f, s1 = 0.f;
    for (int p = p0 + lane; p < p1; p += 32) {
        int   s = g_esrc[p];
        float w = g_enorm[p];
        s0 = fmaf(t2[s * 2],     w, s0);
        s1 = fmaf(t2[s * 2 + 1], w, s1);
    }
    #pragma unroll
    for (int off = 16; off; off >>= 1) {
        s0 += __shfl_xor_sync(0xffffffffu, s0, off);
        s1 += __shfl_xor_sync(0xffffffffu, s1, off);
    }
    if (lane == 0) {
        float ws = g_dis[node];
        ws *= ws;
        out[node * 2]     = s0 + t2[node * 2]     * ws + b3[0];
        out[node * 2 + 1] = s1 + t2[node * 2 + 1] * ws + b3[1];
    }
}

// ---------------- launch ------------------------------------------------------
extern "C" void kernel_launch(void* const* d_in, const int* in_sizes, int n_in,
                              void* d_out, int out_size) {
    const float* x  = (const float*)d_in[0];
    const void*  ei = d_in[1];
    const float* W0 = (const float*)d_in[2];
    const float* b0 = (const float*)d_in[3];
    const float* W1 = (const float*)d_in[4];
    const float* b1 = (const float*)d_in[5];
    const float* W2 = (const float*)d_in[6];
    const float* b2 = (const float*)d_in[7];
    const float* W3 = (const float*)d_in[8];
    const float* b3 = (const float*)d_in[9];
    float* out = (float*)d_out;

    float *T, *HA, *HB, *t2;
    __nv_bfloat16 *Whi, *Wlo;
    cudaGetSymbolAddress((void**)&T,   g_T);
    cudaGetSymbolAddress((void**)&HA,  g_HA);
    cudaGetSymbolAddress((void**)&HB,  g_HB);
    cudaGetSymbolAddress((void**)&t2,  g_t2);
    cudaGetSymbolAddress((void**)&Whi, g_Whi);
    cudaGetSymbolAddress((void**)&Wlo, g_Wlo);

    static int smem_set = 0;
    if (!smem_set) {
        cudaFuncSetAttribute(k_gemm_mma<false>,
                             cudaFuncAttributeMaxDynamicSharedMemorySize, SM_TOT);
        cudaFuncSetAttribute(k_gemm_mma<true>,
                             cudaFuncAttributeMaxDynamicSharedMemorySize, SM_TOT);
        smem_set = 1;
    }

    const int nodeBlocks = (NN + 255) / 256;
    const int edgeBlocks = (EE + 255) / 256;
    const int warpBlocks = (NN + 7) / 8;
    dim3 gemmGrid(NTILES, 2);

    // ---- graph preprocessing ----
    k_detect<<<1, 32>>>((const int*)ei);
    k_init_counts<<<nodeBlocks, 256>>>();
    k_count<<<edgeBlocks, 256>>>(ei);
    k_dis<<<nodeBlocks, 256>>>();
    k_scan<<<1, 1024>>>();
    k_build<<<edgeBlocks, 256>>>(ei);

    // ---- weight split/transpose ----
    k_wsplit<<<256, 256>>>(W0, Whi + 0 * FF * FF, Wlo + 0 * FF * FF);
    k_wsplit<<<256, 256>>>(W1, Whi + 1 * FF * FF, Wlo + 1 * FF * FF);
    k_wsplit<<<256, 256>>>(W2, Whi + 2 * FF * FF, Wlo + 2 * FF * FF);

    // ---- layer 1 ----
    k_gemm_mma<false><<<gemmGrid, 256, SM_TOT>>>(x, Whi, Wlo, T);
    k_agg<<<warpBlocks, 256>>>((const float4*)T, b0, (float4*)HA);
    // ---- layer 2 ----
    k_gemm_mma<true><<<gemmGrid, 256, SM_TOT>>>(HA, Whi + FF * FF, Wlo + FF * FF, T);
    k_agg<<<warpBlocks, 256>>>((const float4*)T, b1, (float4*)HB);
    // ---- layer 3 ----
    k_gemm_mma<true><<<gemmGrid, 256, SM_TOT>>>(HB, Whi + 2 * FF * FF, Wlo + 2 * FF * FF, T);
    k_agg<<<warpBlocks, 256>>>((const float4*)T, b2, (float4*)HA);
    // ---- layer 4 ----
    k_gemm2<<<warpBlocks, 256>>>(HA, W3, t2);
    k_agg2<<<warpBlocks, 256>>>(t2, b3, out);
}